// round 2
// baseline (speedup 1.0000x reference)
#include <cuda_runtime.h>

#define N_NODES 100000
#define THREADS 256

// Scratch: dinv[N] | h[N*64] | h1[N*64] | t2/logits[N*32] | h2[N*32]
__device__ float g_scratch[N_NODES * (1 + 64 + 64 + 32 + 32)];

// ---------------------------------------------------------------- zero
__global__ void k_zero(float4* __restrict__ p, int n4) {
    int i = blockIdx.x * blockDim.x + threadIdx.x;
    int stride = gridDim.x * blockDim.x;
    float4 z = make_float4(0.f, 0.f, 0.f, 0.f);
    for (; i < n4; i += stride) p[i] = z;
}

// ---------------------------------------------------------------- degree
__global__ void k_deg(const int* __restrict__ ei, float* __restrict__ deg, int E) {
    int e = blockIdx.x * blockDim.x + threadIdx.x;
    if (e >= E) return;
    int d = ei[E + e];
    asm volatile("red.global.add.f32 [%0], %1;" :: "l"(deg + d), "f"(1.0f) : "memory");
}

__global__ void k_dinv(float* __restrict__ dinv, int N) {
    int i = blockIdx.x * blockDim.x + threadIdx.x;
    if (i < N) dinv[i] = rsqrtf(dinv[i] + 1.0f);
}

// ---------------------------------------------------------------- GEMM (C = A[M,K] @ B[K,BN], row-major, N fixed = BN)
template<int BM, int BN, int BK, int TM, int TN, bool ACC>
__global__ void k_gemm(const float* __restrict__ A, const float* __restrict__ B,
                       float* __restrict__ C, int M, int K) {
    __shared__ float As[BM][BK + 1];
    __shared__ float Bs[BK][BN];
    constexpr int NT = (BM / TM) * (BN / TN);
    int tid = threadIdx.x;
    int tc = tid % (BN / TN);
    int tr = tid / (BN / TN);
    int rowBase = blockIdx.x * BM;

    float acc[TM][TN];
#pragma unroll
    for (int i = 0; i < TM; i++)
#pragma unroll
        for (int j = 0; j < TN; j++) acc[i][j] = 0.f;

    for (int k0 = 0; k0 < K; k0 += BK) {
#pragma unroll
        for (int i = tid; i < BM * BK; i += NT) {
            int r = i / BK, c = i % BK;
            int gr = rowBase + r;
            As[r][c] = (gr < M) ? A[(size_t)gr * K + k0 + c] : 0.f;
        }
#pragma unroll
        for (int i = tid; i < BK * BN; i += NT) {
            int r = i / BN, c = i % BN;
            Bs[r][c] = B[(size_t)(k0 + r) * BN + c];
        }
        __syncthreads();
#pragma unroll
        for (int kk = 0; kk < BK; kk++) {
            float a[TM], b[TN];
#pragma unroll
            for (int i = 0; i < TM; i++) a[i] = As[tr * TM + i][kk];
#pragma unroll
            for (int j = 0; j < TN; j++) b[j] = Bs[kk][tc * TN + j];
#pragma unroll
            for (int i = 0; i < TM; i++)
#pragma unroll
                for (int j = 0; j < TN; j++) acc[i][j] += a[i] * b[j];
        }
        __syncthreads();
    }
#pragma unroll
    for (int i = 0; i < TM; i++) {
        int gr = rowBase + tr * TM + i;
        if (gr < M) {
#pragma unroll
            for (int j = 0; j < TN; j++) {
                size_t idx = (size_t)gr * BN + tc * TN + j;
                C[idx] = ACC ? (C[idx] + acc[i][j]) : acc[i][j];
            }
        }
    }
}

// ---------------------------------------------------------------- edge scatter: agg[dst] += h[src] * dinv[src]*dinv[dst]
template<int C4>  // number of float4 per row (power of 2)
__global__ void k_scatter(const int* __restrict__ ei, const float* __restrict__ h,
                          const float* __restrict__ dinv, float* __restrict__ agg, int E) {
    int idx = blockIdx.x * blockDim.x + threadIdx.x;
    int total = E * C4;
    if (idx >= total) return;
    int e = idx / C4;
    int q = idx - e * C4;
    int s = ei[e];
    int d = ei[E + e];
    float norm = dinv[s] * dinv[d];
    float4 hv = reinterpret_cast<const float4*>(h)[(size_t)s * C4 + q];
    float4* p = reinterpret_cast<float4*>(agg) + (size_t)d * C4 + q;
    asm volatile("red.global.add.v4.f32 [%0], {%1, %2, %3, %4};"
                 :: "l"(p), "f"(hv.x * norm), "f"(hv.y * norm),
                    "f"(hv.z * norm), "f"(hv.w * norm)
                 : "memory");
}

// ---------------------------------------------------------------- epilogue: agg += h*dinv^2 + b, optional relu
template<int C, bool RELU>
__global__ void k_epi(float* __restrict__ agg, const float* __restrict__ h,
                      const float* __restrict__ dinv, const float* __restrict__ bias, int N) {
    int idx = blockIdx.x * blockDim.x + threadIdx.x;
    if (idx >= N * C) return;
    int node = idx / C;
    int c = idx & (C - 1);
    float di = dinv[node];
    float v = agg[idx] + h[idx] * (di * di) + bias[c];
    agg[idx] = RELU ? fmaxf(v, 0.f) : v;
}

// ---------------------------------------------------------------- log_softmax over 32 cols, warp per node
__global__ void k_lsm(const float* __restrict__ logits, const float* __restrict__ bl,
                      float* __restrict__ out, int N) {
    int node = blockIdx.x * 8 + (threadIdx.x >> 5);
    int lane = threadIdx.x & 31;
    if (node >= N) return;
    float v = logits[(size_t)node * 32 + lane] + bl[lane];
    float m = v;
#pragma unroll
    for (int o = 16; o > 0; o >>= 1) m = fmaxf(m, __shfl_xor_sync(0xffffffffu, m, o));
    float ex = expf(v - m);
    float s = ex;
#pragma unroll
    for (int o = 16; o > 0; o >>= 1) s += __shfl_xor_sync(0xffffffffu, s, o);
    out[(size_t)node * 32 + lane] = v - m - logf(s);
}

// ----------------------------------------------------------------
extern "C" void kernel_launch(void* const* d_in, const int* in_sizes, int n_in,
                              void* d_out, int out_size) {
    const float* x  = (const float*)d_in[0];
    const int*   ei = (const int*)d_in[1];      // int32: JAX x64-disabled downcasts int64->int32
    const float* W1 = (const float*)d_in[2];
    const float* b1 = (const float*)d_in[3];
    const float* W2 = (const float*)d_in[4];
    const float* b2 = (const float*)d_in[5];
    const float* Wl = (const float*)d_in[6];
    const float* bl = (const float*)d_in[7];
    float*       out = (float*)d_out;

    int M = in_sizes[0] / 128;   // 100000
    int E = in_sizes[1] / 2;     // 1600000

    float* scratch = nullptr;
    cudaGetSymbolAddress((void**)&scratch, g_scratch);
    float* dinv = scratch;
    float* h    = dinv + N_NODES;
    float* h1   = h    + (size_t)N_NODES * 64;
    float* t2   = h1   + (size_t)N_NODES * 64;   // reused as logits buffer
    float* h2   = t2   + (size_t)N_NODES * 32;

    // zero deg accumulator + the two scatter destinations
    k_zero<<<256, THREADS>>>((float4*)dinv, M / 4);
    k_zero<<<2048, THREADS>>>((float4*)h1, M * 64 / 4);
    k_zero<<<1024, THREADS>>>((float4*)h2, M * 32 / 4);

    // degree + dinv
    k_deg<<<(E + THREADS - 1) / THREADS, THREADS>>>(ei, dinv, E);
    k_dinv<<<(M + THREADS - 1) / THREADS, THREADS>>>(dinv, M);

    int gemmBlocks = (M + 63) / 64;

    // layer 1: h = x @ W1 ; scatter ; epilogue (+b1, relu) -> h1
    k_gemm<64, 64, 16, 4, 4, false><<<gemmBlocks, THREADS>>>(x, W1, h, M, 128);
    k_scatter<16><<<(E * 16 + THREADS - 1) / THREADS, THREADS>>>(ei, h, dinv, h1, E);
    k_epi<64, true><<<(M * 64 + THREADS - 1) / THREADS, THREADS>>>(h1, h, dinv, b1, M);

    // layer 2: t2 = h1 @ W2 ; scatter ; epilogue (+b2) -> h2
    k_gemm<64, 32, 16, 4, 2, false><<<gemmBlocks, THREADS>>>(h1, W2, t2, M, 64);
    k_scatter<8><<<(E * 8 + THREADS - 1) / THREADS, THREADS>>>(ei, t2, dinv, h2, E);
    k_epi<32, false><<<(M * 32 + THREADS - 1) / THREADS, THREADS>>>(h2, t2, dinv, b2, M);

    // final: logits = [x, h1, h2] @ Wl  (three accumulating GEMMs over row-slices of Wl)
    k_gemm<64, 32, 16, 4, 2, false><<<gemmBlocks, THREADS>>>(x,  Wl,            t2, M, 128);
    k_gemm<64, 32, 16, 4, 2, true ><<<gemmBlocks, THREADS>>>(h1, Wl + 128 * 32, t2, M, 64);
    k_gemm<64, 32, 16, 4, 2, true ><<<gemmBlocks, THREADS>>>(h2, Wl + 192 * 32, t2, M, 32);

    // log_softmax (+bl)
    k_lsm<<<(M + 7) / 8, THREADS>>>(t2, bl, out, M);
}

// round 3
// speedup vs baseline: 1.2993x; 1.2993x over previous
#include <cuda_runtime.h>

#define N_NODES 100000
#define THREADS 256

// Layout: dinv[N] | h1[N*64] | h2agg[N*32] | h[N*64] | t2[N*32] | logits[N*32] | norm[E]
__device__ float g_scratch[(size_t)N_NODES * 225 + 2000000];

// ---------------------------------------------------------------- zero (first N*97 floats: dinv,h1,h2agg)
__global__ void k_zero(float4* __restrict__ p, int n4) {
    int i = blockIdx.x * blockDim.x + threadIdx.x;
    int stride = gridDim.x * blockDim.x;
    float4 z = make_float4(0.f, 0.f, 0.f, 0.f);
    for (; i < n4; i += stride) p[i] = z;
}

// ---------------------------------------------------------------- degree
__global__ void k_deg(const int* __restrict__ ei, float* __restrict__ deg, int E) {
    int e = blockIdx.x * blockDim.x + threadIdx.x;
    if (e >= E) return;
    int d = ei[E + e];
    asm volatile("red.global.add.f32 [%0], %1;" :: "l"(deg + d), "f"(1.0f) : "memory");
}

__global__ void k_dinv(float* __restrict__ dinv, int N) {
    int i = blockIdx.x * blockDim.x + threadIdx.x;
    if (i < N) dinv[i] = rsqrtf(dinv[i] + 1.0f);
}

// ---------------------------------------------------------------- norm[e] = dinv[src]*dinv[dst]
__global__ void k_norm(const int* __restrict__ ei, const float* __restrict__ dinv,
                       float* __restrict__ norm, int E) {
    int e = blockIdx.x * blockDim.x + threadIdx.x;
    if (e >= E) return;
    norm[e] = dinv[ei[e]] * dinv[ei[E + e]];
}

// ---------------------------------------------------------------- GEMM1 fused: [h | logits] = x @ [W1 | Wl0]
// BM=128, BN=96 (64 -> H, 32 -> L), BK=16, K=128, 384 threads, TM=8, TN=4
__global__ __launch_bounds__(384) void k_gemm_f1(
    const float* __restrict__ A, const float* __restrict__ W1, const float* __restrict__ Wl,
    float* __restrict__ H, float* __restrict__ L, int M) {
    __shared__ float As[16][132];
    __shared__ float Bs[16][96];
    int tid = threadIdx.x;
    int tr = tid / 24, tc = tid % 24;
    int rowBase = blockIdx.x * 128;
    float acc[8][4];
#pragma unroll
    for (int i = 0; i < 8; i++)
#pragma unroll
        for (int j = 0; j < 4; j++) acc[i][j] = 0.f;

    for (int k0 = 0; k0 < 128; k0 += 16) {
        for (int i = tid; i < 512; i += 384) {
            int r = i >> 2, c4 = i & 3;
            int gr = rowBase + r;
            float4 v = (gr < M) ? *(const float4*)(A + (size_t)gr * 128 + k0 + c4 * 4)
                                : make_float4(0.f, 0.f, 0.f, 0.f);
            As[c4 * 4 + 0][r] = v.x; As[c4 * 4 + 1][r] = v.y;
            As[c4 * 4 + 2][r] = v.z; As[c4 * 4 + 3][r] = v.w;
        }
        for (int i = tid; i < 1536; i += 384) {
            int r = i / 96, c = i % 96;
            Bs[r][c] = (c < 64) ? W1[(size_t)(k0 + r) * 64 + c]
                                : Wl[(size_t)(k0 + r) * 32 + (c - 64)];
        }
        __syncthreads();
#pragma unroll
        for (int kk = 0; kk < 16; kk++) {
            float4 a0 = *(const float4*)&As[kk][tr * 8];
            float4 a1 = *(const float4*)&As[kk][tr * 8 + 4];
            float4 bv = *(const float4*)&Bs[kk][tc * 4];
            float a[8] = {a0.x, a0.y, a0.z, a0.w, a1.x, a1.y, a1.z, a1.w};
            float b[4] = {bv.x, bv.y, bv.z, bv.w};
#pragma unroll
            for (int i = 0; i < 8; i++)
#pragma unroll
                for (int j = 0; j < 4; j++) acc[i][j] += a[i] * b[j];
        }
        __syncthreads();
    }
#pragma unroll
    for (int i = 0; i < 8; i++) {
        int gr = rowBase + tr * 8 + i;
        if (gr >= M) continue;
        float4 v = make_float4(acc[i][0], acc[i][1], acc[i][2], acc[i][3]);
        if (tc < 16) *(float4*)(H + (size_t)gr * 64 + tc * 4) = v;
        else         *(float4*)(L + (size_t)gr * 32 + (tc - 16) * 4) = v;
    }
}

// ---------------------------------------------------------------- GEMM2 fused: [t2 | logits+=] = h1 @ [W2 | Wl1]
// BM=128, BN=64 (32 -> t2, 32 -> L accumulate), BK=16, K=64, 256 threads
__global__ __launch_bounds__(256) void k_gemm_f2(
    const float* __restrict__ A, const float* __restrict__ W2, const float* __restrict__ Wl,
    float* __restrict__ T2, float* __restrict__ L, int M) {
    __shared__ float As[16][132];
    __shared__ float Bs[16][64];
    int tid = threadIdx.x;
    int tr = tid / 16, tc = tid % 16;
    int rowBase = blockIdx.x * 128;
    float acc[8][4];
#pragma unroll
    for (int i = 0; i < 8; i++)
#pragma unroll
        for (int j = 0; j < 4; j++) acc[i][j] = 0.f;

    for (int k0 = 0; k0 < 64; k0 += 16) {
        for (int i = tid; i < 512; i += 256) {
            int r = i >> 2, c4 = i & 3;
            int gr = rowBase + r;
            float4 v = (gr < M) ? *(const float4*)(A + (size_t)gr * 64 + k0 + c4 * 4)
                                : make_float4(0.f, 0.f, 0.f, 0.f);
            As[c4 * 4 + 0][r] = v.x; As[c4 * 4 + 1][r] = v.y;
            As[c4 * 4 + 2][r] = v.z; As[c4 * 4 + 3][r] = v.w;
        }
        for (int i = tid; i < 1024; i += 256) {
            int r = i / 64, c = i % 64;
            Bs[r][c] = (c < 32) ? W2[(size_t)(k0 + r) * 32 + c]
                                : Wl[(size_t)(128 + k0 + r) * 32 + (c - 32)];
        }
        __syncthreads();
#pragma unroll
        for (int kk = 0; kk < 16; kk++) {
            float4 a0 = *(const float4*)&As[kk][tr * 8];
            float4 a1 = *(const float4*)&As[kk][tr * 8 + 4];
            float4 bv = *(const float4*)&Bs[kk][tc * 4];
            float a[8] = {a0.x, a0.y, a0.z, a0.w, a1.x, a1.y, a1.z, a1.w};
            float b[4] = {bv.x, bv.y, bv.z, bv.w};
#pragma unroll
            for (int i = 0; i < 8; i++)
#pragma unroll
                for (int j = 0; j < 4; j++) acc[i][j] += a[i] * b[j];
        }
        __syncthreads();
    }
#pragma unroll
    for (int i = 0; i < 8; i++) {
        int gr = rowBase + tr * 8 + i;
        if (gr >= M) continue;
        if (tc < 8) {
            *(float4*)(T2 + (size_t)gr * 32 + tc * 4) =
                make_float4(acc[i][0], acc[i][1], acc[i][2], acc[i][3]);
        } else {
            float* p = L + (size_t)gr * 32 + (tc - 8) * 4;
            float4 old = *(float4*)p;
            *(float4*)p = make_float4(old.x + acc[i][0], old.y + acc[i][1],
                                      old.z + acc[i][2], old.w + acc[i][3]);
        }
    }
}

// ---------------------------------------------------------------- GEMM3 fused: logits += (h2agg + t2*dinv^2 + b2) @ Wl2
// BM=128, BN=32, K=32 (single tile), 128 threads
__global__ __launch_bounds__(128) void k_gemm_f3(
    const float* __restrict__ AGG, const float* __restrict__ T2,
    const float* __restrict__ dinv, const float* __restrict__ b2,
    const float* __restrict__ Wl2, float* __restrict__ L, int M) {
    __shared__ float As[32][132];
    __shared__ float Bs[32][32];
    int tid = threadIdx.x;
    int tr = tid / 8, tc = tid % 8;
    int rowBase = blockIdx.x * 128;

    for (int i = tid; i < 1024; i += 128) {   // 128*32/4 float4
        int r = i >> 3, c4 = i & 7;
        int gr = rowBase + r;
        float4 v = make_float4(0.f, 0.f, 0.f, 0.f);
        if (gr < M) {
            float di = dinv[gr]; float d2 = di * di;
            float4 ag = *(const float4*)(AGG + (size_t)gr * 32 + c4 * 4);
            float4 tv = *(const float4*)(T2  + (size_t)gr * 32 + c4 * 4);
            float4 bv = *(const float4*)(b2 + c4 * 4);
            v = make_float4(ag.x + tv.x * d2 + bv.x, ag.y + tv.y * d2 + bv.y,
                            ag.z + tv.z * d2 + bv.z, ag.w + tv.w * d2 + bv.w);
        }
        As[c4 * 4 + 0][r] = v.x; As[c4 * 4 + 1][r] = v.y;
        As[c4 * 4 + 2][r] = v.z; As[c4 * 4 + 3][r] = v.w;
    }
    for (int i = tid; i < 1024; i += 128) Bs[i >> 5][i & 31] = Wl2[i];
    __syncthreads();

    float acc[8][4];
#pragma unroll
    for (int i = 0; i < 8; i++)
#pragma unroll
        for (int j = 0; j < 4; j++) acc[i][j] = 0.f;
#pragma unroll
    for (int kk = 0; kk < 32; kk++) {
        float4 a0 = *(const float4*)&As[kk][tr * 8];
        float4 a1 = *(const float4*)&As[kk][tr * 8 + 4];
        float4 bv = *(const float4*)&Bs[kk][tc * 4];
        float a[8] = {a0.x, a0.y, a0.z, a0.w, a1.x, a1.y, a1.z, a1.w};
        float b[4] = {bv.x, bv.y, bv.z, bv.w};
#pragma unroll
        for (int i = 0; i < 8; i++)
#pragma unroll
            for (int j = 0; j < 4; j++) acc[i][j] += a[i] * b[j];
    }
#pragma unroll
    for (int i = 0; i < 8; i++) {
        int gr = rowBase + tr * 8 + i;
        if (gr >= M) continue;
        float* p = L + (size_t)gr * 32 + tc * 4;
        float4 old = *(float4*)p;
        *(float4*)p = make_float4(old.x + acc[i][0], old.y + acc[i][1],
                                  old.z + acc[i][2], old.w + acc[i][3]);
    }
}

// ---------------------------------------------------------------- edge scatter: agg[dst] += h[src]*norm[e]
template<int C4>
__global__ void k_scatter(const int* __restrict__ ei, const float* __restrict__ norm,
                          const float* __restrict__ h, float* __restrict__ agg, int E) {
    int idx = blockIdx.x * blockDim.x + threadIdx.x;
    if (idx >= E * C4) return;
    int e = idx / C4;
    int q = idx - e * C4;
    int s = ei[e];
    int d = ei[E + e];
    float nrm = norm[e];
    float4 hv = reinterpret_cast<const float4*>(h)[(size_t)s * C4 + q];
    float4* p = reinterpret_cast<float4*>(agg) + (size_t)d * C4 + q;
    asm volatile("red.global.add.v4.f32 [%0], {%1, %2, %3, %4};"
                 :: "l"(p), "f"(hv.x * nrm), "f"(hv.y * nrm),
                    "f"(hv.z * nrm), "f"(hv.w * nrm)
                 : "memory");
}

// ---------------------------------------------------------------- epi1: h1 = relu(h1agg + h*dinv^2 + b1)
__global__ void k_epi1(float* __restrict__ h1, const float* __restrict__ h,
                       const float* __restrict__ dinv, const float* __restrict__ b1, int N) {
    int idx = blockIdx.x * blockDim.x + threadIdx.x;   // over N*16 float4
    if (idx >= N * 16) return;
    int node = idx >> 4;
    int c4 = idx & 15;
    float di = dinv[node]; float d2 = di * di;
    float4 ag = *(float4*)(h1 + (size_t)idx * 4);
    float4 hv = *(const float4*)(h + (size_t)idx * 4);
    float4 bv = *(const float4*)(b1 + c4 * 4);
    float4 v = make_float4(fmaxf(ag.x + hv.x * d2 + bv.x, 0.f),
                           fmaxf(ag.y + hv.y * d2 + bv.y, 0.f),
                           fmaxf(ag.z + hv.z * d2 + bv.z, 0.f),
                           fmaxf(ag.w + hv.w * d2 + bv.w, 0.f));
    *(float4*)(h1 + (size_t)idx * 4) = v;
}

// ---------------------------------------------------------------- log_softmax over 32 cols, warp per node
__global__ void k_lsm(const float* __restrict__ logits, const float* __restrict__ bl,
                      float* __restrict__ out, int N) {
    int node = blockIdx.x * 8 + (threadIdx.x >> 5);
    int lane = threadIdx.x & 31;
    if (node >= N) return;
    float v = logits[(size_t)node * 32 + lane] + bl[lane];
    float m = v;
#pragma unroll
    for (int o = 16; o > 0; o >>= 1) m = fmaxf(m, __shfl_xor_sync(0xffffffffu, m, o));
    float ex = expf(v - m);
    float s = ex;
#pragma unroll
    for (int o = 16; o > 0; o >>= 1) s += __shfl_xor_sync(0xffffffffu, s, o);
    out[(size_t)node * 32 + lane] = v - m - logf(s);
}

// ----------------------------------------------------------------
extern "C" void kernel_launch(void* const* d_in, const int* in_sizes, int n_in,
                              void* d_out, int out_size) {
    const float* x  = (const float*)d_in[0];
    const int*   ei = (const int*)d_in[1];
    const float* W1 = (const float*)d_in[2];
    const float* b1 = (const float*)d_in[3];
    const float* W2 = (const float*)d_in[4];
    const float* b2 = (const float*)d_in[5];
    const float* Wl = (const float*)d_in[6];
    const float* bl = (const float*)d_in[7];
    float*       out = (float*)d_out;

    int M = in_sizes[0] / 128;   // 100000
    int E = in_sizes[1] / 2;     // 1600000

    float* s = nullptr;
    cudaGetSymbolAddress((void**)&s, g_scratch);
    float* dinv   = s;
    float* h1     = dinv + N_NODES;
    float* h2agg  = h1 + (size_t)N_NODES * 64;
    float* h      = h2agg + (size_t)N_NODES * 32;
    float* t2     = h + (size_t)N_NODES * 64;
    float* logits = t2 + (size_t)N_NODES * 32;
    float* norm   = logits + (size_t)N_NODES * 32;

    // zero dinv + h1 + h2agg (contiguous: N*97 floats)
    k_zero<<<2048, THREADS>>>((float4*)dinv, M * 97 / 4);

    k_deg<<<(E + THREADS - 1) / THREADS, THREADS>>>(ei, dinv, E);
    k_dinv<<<(M + THREADS - 1) / THREADS, THREADS>>>(dinv, M);
    k_norm<<<(E + THREADS - 1) / THREADS, THREADS>>>(ei, dinv, norm, E);

    int gb = (M + 127) / 128;

    // layer 1 (+ x@Wl0)
    k_gemm_f1<<<gb, 384>>>(x, W1, Wl, h, logits, M);
    k_scatter<16><<<(E * 16 + THREADS - 1) / THREADS, THREADS>>>(ei, norm, h, h1, E);
    k_epi1<<<(M * 16 + THREADS - 1) / THREADS, THREADS>>>(h1, h, dinv, b1, M);

    // layer 2 (+ h1@Wl1)
    k_gemm_f2<<<gb, 256>>>(h1, W2, Wl, t2, logits, M);
    k_scatter<8><<<(E * 8 + THREADS - 1) / THREADS, THREADS>>>(ei, norm, t2, h2agg, E);

    // final: epilogue-fused h2 @ Wl2
    k_gemm_f3<<<gb, 128>>>(h2agg, t2, dinv, b2, Wl + 192 * 32, logits, M);

    // log_softmax
    k_lsm<<<(M + 7) / 8, THREADS>>>(logits, bl, out, M);
}